// round 15
// baseline (speedup 1.0000x reference)
#include <cuda_runtime.h>
#include <cuda_fp16.h>
#include <math.h>

#define IMW 1024
#define IMH 1024
#define NB  8
#define OW  128
#define OH  32
#define LW  160          // luma tile cols: global x in [x0-16, x0+144)
#define LH  62           // luma tile rows: global y in [y0-15, y0+47)
#define SWH 160          // stride: halves (sLuma/sV7), floats (sV31)
#define NT  256
// smem: sLuma 62*160*2 + sV31 32*160*4 + sV7 32*160*2 = 19840+20480+10240 = 50560 B
// -> 4 CTAs/SM (202.2KB of 228KB)
#define SMEM_BYTES (LH*SWH*2 + OH*SWH*4 + OH*SWH*2)

// 31-tap gaussian (sigma=8), normalized, k=0..30 (center 15)
__device__ constexpr float G31[31] = {
    0.0090750f, 0.0113825f, 0.0140557f, 0.0170873f, 0.0204508f, 0.0240970f,
    0.0279530f, 0.0319233f, 0.0358923f, 0.0397292f, 0.0432944f, 0.0464481f,
    0.0490592f, 0.0510133f, 0.0522230f, 0.0526326f, 0.0522230f, 0.0510133f,
    0.0490592f, 0.0464481f, 0.0432944f, 0.0397292f, 0.0358923f, 0.0319233f,
    0.0279530f, 0.0240970f, 0.0204508f, 0.0170873f, 0.0140557f, 0.0113825f,
    0.0090750f
};
// 7-tap gaussian (sigma=1.5), normalized
__device__ constexpr float G7[7] = {
    0.0366328f, 0.1112808f, 0.2167454f, 0.2706822f,
    0.2167454f, 0.1112808f, 0.0366328f
};

__global__ __launch_bounds__(NT, 4)
void clarity_texture_kernel(const float* __restrict__ x,
                            const float* __restrict__ clar,
                            const float* __restrict__ tex,
                            float* __restrict__ out) {
    extern __shared__ __half smem[];
    __half* sLuma = smem;                              // LH x SWH halves
    float*  sV31  = (float*)(smem + LH * SWH);         // OH x SWH floats
    __half* sV7   = (__half*)(sV31 + OH * SWH);        // OH x SWH halves

    const int tid = threadIdx.x;
    const int x0  = blockIdx.x * OW;
    const int y0  = blockIdx.y * OH;
    const int b   = blockIdx.z;

    const float ca = tanhf(*clar) * 0.5f;
    const float ta = tanhf(*tex) * 0.3f;

    const size_t plane = (size_t)IMH * IMW;
    const float* xb = x + (size_t)b * 3 * plane;
    float* ob = out + (size_t)b * 3 * plane;

    // ---- Phase 1: luma tile with halo (fp16 store), float4 global loads ----
    for (int i = tid; i < LH * (LW / 4); i += NT) {
        int row = i / (LW / 4);
        int cc  = i % (LW / 4);
        int gy  = y0 - 15 + row;
        int gx  = x0 - 16 + cc * 4;
        float4 l4 = make_float4(0.f, 0.f, 0.f, 0.f);
        if ((unsigned)gy < IMH && (unsigned)gx < IMW) {
            size_t idx = (size_t)gy * IMW + gx;
            float4 r4 = *(const float4*)&xb[idx];
            float4 g4 = *(const float4*)&xb[idx + plane];
            float4 b4 = *(const float4*)&xb[idx + 2 * plane];
            l4.x = 0.2126f * r4.x + 0.7152f * g4.x + 0.0722f * b4.x;
            l4.y = 0.2126f * r4.y + 0.7152f * g4.y + 0.0722f * b4.y;
            l4.z = 0.2126f * r4.z + 0.7152f * g4.z + 0.0722f * b4.z;
            l4.w = 0.2126f * r4.w + 0.7152f * g4.w + 0.0722f * b4.w;
        }
        __half2 h0 = __floats2half2_rn(l4.x, l4.y);
        __half2 h1 = __floats2half2_rn(l4.z, l4.w);
        uint2 pk;
        pk.x = *(unsigned*)&h0;
        pk.y = *(unsigned*)&h1;
        *(uint2*)&sLuma[row * SWH + cc * 4] = pk;
    }
    __syncthreads();

    // ---- Phase 2: vertical 31-tap AND 7-tap blurs, 2 cols x 4 rows/thread ----
    for (int s = tid; s < (SWH / 2) * (OH / 4); s += NT) {   // 80*8 = 640
        int c  = s % (SWH / 2);
        int r0 = (s / (SWH / 2)) * 4;
        float2 a[4] = {{0.f,0.f},{0.f,0.f},{0.f,0.f},{0.f,0.f}};
        float2 w[4] = {{0.f,0.f},{0.f,0.f},{0.f,0.f},{0.f,0.f}};
        #pragma unroll
        for (int k = 0; k < 34; k++) {
            float2 v = __half22float2(*(const __half2*)&sLuma[(r0 + k) * SWH + 2 * c]);
            #pragma unroll
            for (int o = 0; o < 4; o++) {
                int i31 = k - o;
                if (i31 >= 0 && i31 < 31) {          // FFMA-imm weights
                    a[o].x += G31[i31] * v.x;
                    a[o].y += G31[i31] * v.y;
                }
                int j7 = k - 12 - o;                 // 7-tap: luma rows r0+o+12..+18
                if (j7 >= 0 && j7 < 7) {
                    w[o].x += G7[j7] * v.x;
                    w[o].y += G7[j7] * v.y;
                }
            }
        }
        #pragma unroll
        for (int o = 0; o < 4; o++) {
            *(float2*)&sV31[(r0 + o) * SWH + 2 * c] = a[o];                       // STS.64
            *(__half2*)&sV7 [(r0 + o) * SWH + 2 * c] = __floats2half2_rn(w[o].x, w[o].y);
        }
    }
    __syncthreads();

    // ---- Phase 3: horizontal blurs + combine + clip, 8 output cols/thread ----
    for (int s = tid; s < OH * (OW / 8); s += NT) {   // 32*16 = 512 items
        int strip = s & 15;
        int r     = s >> 4;
        int c0    = strip * 8;

        // 7-tap first (small live range): taps sV7 cols c0+13+o+j (j=0..6);
        // aligned window starts at c0+8, uses e2[5..19].
        float a7[8];
        {
            float e2[24];
            const uint4* q4 = (const uint4*)&sV7[r * SWH + c0 + 8];
            #pragma unroll
            for (int chk = 0; chk < 3; chk++) {
                uint4 u = q4[chk];
                float2 f;
                f = __half22float2(*(__half2*)&u.x); e2[chk*8+0]=f.x; e2[chk*8+1]=f.y;
                f = __half22float2(*(__half2*)&u.y); e2[chk*8+2]=f.x; e2[chk*8+3]=f.y;
                f = __half22float2(*(__half2*)&u.z); e2[chk*8+4]=f.x; e2[chk*8+5]=f.y;
                f = __half22float2(*(__half2*)&u.w); e2[chk*8+6]=f.x; e2[chk*8+7]=f.y;
            }
            #pragma unroll
            for (int o = 0; o < 8; o++) {
                float acc = 0.f;
                #pragma unroll
                for (int j = 0; j < 7; j++) acc += G7[j] * e2[5 + o + j];
                a7[o] = acc;
            }
        }

        // 31-tap horizontal over fp32 plane: taps cols c0+1+o .. c0+31+o,
        // window floats c0..c0+39 = 10 float4 chunks, no converts.
        float a31[8] = {0.f,0.f,0.f,0.f,0.f,0.f,0.f,0.f};
        const float4* p31 = (const float4*)&sV31[r * SWH + c0];
        #pragma unroll
        for (int chk = 0; chk < 10; chk++) {
            float4 v4 = p31[chk];
            float e[4] = {v4.x, v4.y, v4.z, v4.w};
            #pragma unroll
            for (int q = 0; q < 4; q++) {
                int M = chk * 4 + q;
                #pragma unroll
                for (int o = 0; o < 8; o++) {
                    int k = M - 1 - o;
                    if (k >= 0 && k < 31) a31[o] += G31[k] * e[q];
                }
            }
        }

        // center luma (8 halves, one LDS.128) -> ratio
        float ratio[8];
        {
            uint4 u = *(const uint4*)&sLuma[(r + 15) * SWH + c0 + 16];
            float lum[8];
            float2 f;
            f = __half22float2(*(__half2*)&u.x); lum[0]=f.x; lum[1]=f.y;
            f = __half22float2(*(__half2*)&u.y); lum[2]=f.x; lum[3]=f.y;
            f = __half22float2(*(__half2*)&u.z); lum[4]=f.x; lum[5]=f.y;
            f = __half22float2(*(__half2*)&u.w); lum[6]=f.x; lum[7]=f.y;
            #pragma unroll
            for (int o = 0; o < 8; o++) {
                float le = lum[o] + ca * (lum[o] - a31[o]) + ta * (lum[o] - a7[o]);
                ratio[o] = __fdividef(le + 1e-6f, lum[o] + 1e-6f);
            }
        }

        int gy = y0 + r;
        int gx = x0 + c0;
        size_t idx = (size_t)gy * IMW + gx;
        #pragma unroll
        for (int ch = 0; ch < 3; ch++) {
            size_t o0 = idx + (size_t)ch * plane;
            float4 xa = *(const float4*)&xb[o0];
            float4 xc = *(const float4*)&xb[o0 + 4];
            float4 ra, rc;
            ra.x = __saturatef(xa.x * ratio[0]); ra.y = __saturatef(xa.y * ratio[1]);
            ra.z = __saturatef(xa.z * ratio[2]); ra.w = __saturatef(xa.w * ratio[3]);
            rc.x = __saturatef(xc.x * ratio[4]); rc.y = __saturatef(xc.y * ratio[5]);
            rc.z = __saturatef(xc.z * ratio[6]); rc.w = __saturatef(xc.w * ratio[7]);
            *(float4*)&ob[o0]     = ra;
            *(float4*)&ob[o0 + 4] = rc;
        }
    }
}

extern "C" void kernel_launch(void* const* d_in, const int* in_sizes, int n_in,
                              void* d_out, int out_size) {
    const float* x    = (const float*)d_in[0];
    const float* clar = (const float*)d_in[1];
    const float* tex  = (const float*)d_in[2];
    float* out = (float*)d_out;

    cudaFuncSetAttribute(clarity_texture_kernel,
                         cudaFuncAttributeMaxDynamicSharedMemorySize, SMEM_BYTES);

    dim3 grid(IMW / OW, IMH / OH, NB);
    clarity_texture_kernel<<<grid, NT, SMEM_BYTES>>>(x, clar, tex, out);
}

// round 16
// speedup vs baseline: 1.2524x; 1.2524x over previous
#include <cuda_runtime.h>
#include <cuda_fp16.h>
#include <math.h>

#define IMW 1024
#define IMH 1024
#define NB  8
#define OW  128
#define OH  32
#define LW  160          // luma tile cols: global x in [x0-16, x0+144)
#define LH  62           // luma tile rows: global y in [y0-15, y0+47)
#define SWH 160          // shared row stride in halves (320 bytes)
#define NT  256
// smem: (62+32+32)*160*2 = 40320 B -> 4 CTAs/SM
#define SMEM_BYTES ((LH + OH + OH) * SWH * 2)

// 31-tap gaussian (sigma=8), normalized, k=0..30 (center 15) -- fp32 for phase 3
__device__ constexpr float G31[31] = {
    0.0090750f, 0.0113825f, 0.0140557f, 0.0170873f, 0.0204508f, 0.0240970f,
    0.0279530f, 0.0319233f, 0.0358923f, 0.0397292f, 0.0432944f, 0.0464481f,
    0.0490592f, 0.0510133f, 0.0522230f, 0.0526326f, 0.0522230f, 0.0510133f,
    0.0490592f, 0.0464481f, 0.0432944f, 0.0397292f, 0.0358923f, 0.0319233f,
    0.0279530f, 0.0240970f, 0.0204508f, 0.0170873f, 0.0140557f, 0.0113825f,
    0.0090750f
};
// 7-tap gaussian (sigma=1.5), normalized -- fp32 for phase 3
__device__ constexpr float G7[7] = {
    0.0366328f, 0.1112808f, 0.2167454f, 0.2706822f,
    0.2167454f, 0.1112808f, 0.0366328f
};
// Same weights as fp16x2 immediates (both lanes equal) -- phase 2 HFMA2
__device__ constexpr unsigned G31X2[31] = {
    0x20A520A5u, 0x21D421D4u, 0x23322332u, 0x24602460u, 0x253C253Cu, 0x262B262Bu,
    0x27282728u, 0x28162816u, 0x28982898u, 0x29162916u, 0x298B298Bu, 0x29F229F2u,
    0x2A482A48u, 0x2A882A88u, 0x2AAF2AAFu, 0x2ABD2ABDu, 0x2AAF2AAFu, 0x2A882A88u,
    0x2A482A48u, 0x29F229F2u, 0x298B298Bu, 0x29162916u, 0x28982898u, 0x28162816u,
    0x27282728u, 0x262B262Bu, 0x253C253Cu, 0x24602460u, 0x23322332u, 0x21D421D4u,
    0x20A520A5u
};
__device__ constexpr unsigned G7X2[7] = {
    0x28B028B0u, 0x2F1F2F1Fu, 0x32F032F0u, 0x34553455u,
    0x32F032F0u, 0x2F1F2F1Fu, 0x28B028B0u
};

__device__ __forceinline__ __half2 hc(unsigned b) {
    __half2_raw r;
    r.x = (unsigned short)(b & 0xFFFFu);
    r.y = (unsigned short)(b >> 16);
    return __half2(r);
}

__global__ __launch_bounds__(NT, 4)
void clarity_texture_kernel(const float* __restrict__ x,
                            const float* __restrict__ clar,
                            const float* __restrict__ tex,
                            float* __restrict__ out) {
    extern __shared__ __half smem[];
    __half* sLuma = smem;                 // LH x SWH
    __half* sV31  = smem + LH * SWH;      // OH x SWH  (vertical 31-tap)
    __half* sV7   = sV31 + OH * SWH;      // OH x SWH  (vertical 7-tap)

    const int tid = threadIdx.x;
    const int x0  = blockIdx.x * OW;
    const int y0  = blockIdx.y * OH;
    const int b   = blockIdx.z;

    const float ca = tanhf(*clar) * 0.5f;
    const float ta = tanhf(*tex) * 0.3f;

    const size_t plane = (size_t)IMH * IMW;
    const float* xb = x + (size_t)b * 3 * plane;
    float* ob = out + (size_t)b * 3 * plane;

    // ---- Phase 1: luma tile with halo (fp16 store), float4 global loads ----
    for (int i = tid; i < LH * (LW / 4); i += NT) {
        int row = i / (LW / 4);
        int cc  = i % (LW / 4);
        int gy  = y0 - 15 + row;
        int gx  = x0 - 16 + cc * 4;
        float4 l4 = make_float4(0.f, 0.f, 0.f, 0.f);
        if ((unsigned)gy < IMH && (unsigned)gx < IMW) {
            size_t idx = (size_t)gy * IMW + gx;
            float4 r4 = *(const float4*)&xb[idx];
            float4 g4 = *(const float4*)&xb[idx + plane];
            float4 b4 = *(const float4*)&xb[idx + 2 * plane];
            l4.x = 0.2126f * r4.x + 0.7152f * g4.x + 0.0722f * b4.x;
            l4.y = 0.2126f * r4.y + 0.7152f * g4.y + 0.0722f * b4.y;
            l4.z = 0.2126f * r4.z + 0.7152f * g4.z + 0.0722f * b4.z;
            l4.w = 0.2126f * r4.w + 0.7152f * g4.w + 0.0722f * b4.w;
        }
        __half2 h0 = __floats2half2_rn(l4.x, l4.y);
        __half2 h1 = __floats2half2_rn(l4.z, l4.w);
        uint2 pk;
        pk.x = *(unsigned*)&h0;
        pk.y = *(unsigned*)&h1;
        *(uint2*)&sLuma[row * SWH + cc * 4] = pk;
    }
    __syncthreads();

    // ---- Phase 2: vertical 31-tap AND 7-tap blurs, HFMA2, 2 cols x 4 rows ----
    for (int s = tid; s < (SWH / 2) * (OH / 4); s += NT) {   // 80*8 = 640
        int c  = s % (SWH / 2);
        int r0 = (s / (SWH / 2)) * 4;
        __half2 a[4], w[4];
        #pragma unroll
        for (int o = 0; o < 4; o++) { a[o] = hc(0u); w[o] = hc(0u); }
        #pragma unroll
        for (int k = 0; k < 34; k++) {
            __half2 v = *(const __half2*)&sLuma[(r0 + k) * SWH + 2 * c];
            #pragma unroll
            for (int o = 0; o < 4; o++) {
                int i31 = k - o;
                if (i31 >= 0 && i31 < 31) a[o] = __hfma2(v, hc(G31X2[i31]), a[o]);
                int j7 = k - 12 - o;                 // 7-tap: luma rows r0+o+12..+18
                if (j7 >= 0 && j7 < 7)    w[o] = __hfma2(v, hc(G7X2[j7]), w[o]);
            }
        }
        #pragma unroll
        for (int o = 0; o < 4; o++) {
            *(__half2*)&sV31[(r0 + o) * SWH + 2 * c] = a[o];
            *(__half2*)&sV7 [(r0 + o) * SWH + 2 * c] = w[o];
        }
    }
    __syncthreads();

    // ---- Phase 3: horizontal blurs + combine + clip, 8 output cols/thread ----
    for (int s = tid; s < OH * (OW / 8); s += NT) {   // 32*16 = 512 items
        int strip = s & 15;
        int r     = s >> 4;
        int c0    = strip * 8;

        // 31-tap horizontal: taps sV31 cols c0+1+o .. c0+31+o, window c0..c0+39.
        float a31[8] = {0.f,0.f,0.f,0.f,0.f,0.f,0.f,0.f};
        const uint4* p31 = (const uint4*)&sV31[r * SWH + c0];
        #pragma unroll
        for (int chk = 0; chk < 5; chk++) {
            uint4 u = p31[chk];
            float e[8];
            {
                float2 f;
                f = __half22float2(*(__half2*)&u.x); e[0]=f.x; e[1]=f.y;
                f = __half22float2(*(__half2*)&u.y); e[2]=f.x; e[3]=f.y;
                f = __half22float2(*(__half2*)&u.z); e[4]=f.x; e[5]=f.y;
                f = __half22float2(*(__half2*)&u.w); e[6]=f.x; e[7]=f.y;
            }
            #pragma unroll
            for (int m = 0; m < 8; m++) {
                int M = chk * 8 + m;
                #pragma unroll
                for (int o = 0; o < 8; o++) {
                    int k = M - 1 - o;
                    if (k >= 0 && k < 31) a31[o] += G31[k] * e[m];
                }
            }
        }

        // 7-tap horizontal over precomputed vertical 7-tap plane.
        // Taps sV7 cols c0+13+o+j (j=0..6); aligned window starts at c0+8.
        float e2[24];
        {
            const uint4* q4 = (const uint4*)&sV7[r * SWH + c0 + 8];
            #pragma unroll
            for (int chk = 0; chk < 3; chk++) {
                uint4 u = q4[chk];
                float2 f;
                f = __half22float2(*(__half2*)&u.x); e2[chk*8+0]=f.x; e2[chk*8+1]=f.y;
                f = __half22float2(*(__half2*)&u.y); e2[chk*8+2]=f.x; e2[chk*8+3]=f.y;
                f = __half22float2(*(__half2*)&u.z); e2[chk*8+4]=f.x; e2[chk*8+5]=f.y;
                f = __half22float2(*(__half2*)&u.w); e2[chk*8+6]=f.x; e2[chk*8+7]=f.y;
            }
        }
        float a7[8];
        #pragma unroll
        for (int o = 0; o < 8; o++) {
            float acc = 0.f;
            #pragma unroll
            for (int j = 0; j < 7; j++) acc += G7[j] * e2[5 + o + j];
            a7[o] = acc;
        }

        // center luma (8 halves, one LDS.128)
        float lum[8];
        {
            uint4 u = *(const uint4*)&sLuma[(r + 15) * SWH + c0 + 16];
            float2 f;
            f = __half22float2(*(__half2*)&u.x); lum[0]=f.x; lum[1]=f.y;
            f = __half22float2(*(__half2*)&u.y); lum[2]=f.x; lum[3]=f.y;
            f = __half22float2(*(__half2*)&u.z); lum[4]=f.x; lum[5]=f.y;
            f = __half22float2(*(__half2*)&u.w); lum[6]=f.x; lum[7]=f.y;
        }

        float ratio[8];
        #pragma unroll
        for (int o = 0; o < 8; o++) {
            float le = lum[o] + ca * (lum[o] - a31[o]) + ta * (lum[o] - a7[o]);
            ratio[o] = __fdividef(le + 1e-6f, lum[o] + 1e-6f);
        }

        int gy = y0 + r;
        int gx = x0 + c0;
        size_t idx = (size_t)gy * IMW + gx;
        #pragma unroll
        for (int ch = 0; ch < 3; ch++) {
            size_t o0 = idx + (size_t)ch * plane;
            float4 xa = *(const float4*)&xb[o0];
            float4 xc = *(const float4*)&xb[o0 + 4];
            float4 ra, rc;
            ra.x = __saturatef(xa.x * ratio[0]); ra.y = __saturatef(xa.y * ratio[1]);
            ra.z = __saturatef(xa.z * ratio[2]); ra.w = __saturatef(xa.w * ratio[3]);
            rc.x = __saturatef(xc.x * ratio[4]); rc.y = __saturatef(xc.y * ratio[5]);
            rc.z = __saturatef(xc.z * ratio[6]); rc.w = __saturatef(xc.w * ratio[7]);
            *(float4*)&ob[o0]     = ra;
            *(float4*)&ob[o0 + 4] = rc;
        }
    }
}

extern "C" void kernel_launch(void* const* d_in, const int* in_sizes, int n_in,
                              void* d_out, int out_size) {
    const float* x    = (const float*)d_in[0];
    const float* clar = (const float*)d_in[1];
    const float* tex  = (const float*)d_in[2];
    float* out = (float*)d_out;

    cudaFuncSetAttribute(clarity_texture_kernel,
                         cudaFuncAttributeMaxDynamicSharedMemorySize, SMEM_BYTES);

    dim3 grid(IMW / OW, IMH / OH, NB);
    clarity_texture_kernel<<<grid, NT, SMEM_BYTES>>>(x, clar, tex, out);
}